// round 17
// baseline (speedup 1.0000x reference)
#include <cuda_runtime.h>
#include <cstdint>

// MonarchOutProjection:
//   h2[t][m][q]   = sum_k L[m][q][k] * x[t][32k+m]
//   out[t][32p+q] = sum_m R[q][p][m] * h2[t][m][q]
//
// R9: MOV-elimination via q-paired f32x2 operands.
//  - grid (37,4) = 148 persistent CTAs, 8 q/CTA, 96-token tiles, 768 threads.
//  - Weights in stride-10 smem rows: Ls[(k*32+m)*10+q], Rs[(p*32+m)*10+q].
//    LDS.64 at +2*qp yields the (q,q+1) f32x2 operand directly (0 MOVs),
//    stride 10 floats (40B) => conflict-free 16-lane phases for LDS.64.
//  - Stage1: warp w: tokens [4w,4w+4), acc[qpair=4][tok=4]; x dup'd (pack2).
//  - Stage2: warp w: qp2=w&3, tg=w>>2, tokens [16tg,16tg+16) in 2 phases of 8;
//    R via LDS.64 (0 MOV), h via float4 broadcast of stage1's ull pairs.
//  - h2: ull[qp][t][m] = 96KB. outs: 48 slots x 256 f, (p^(q<<2)) swizzle.
//  - smem: Ls 40K + Rs 40K + h2 96K + outs 48K = 229376 B. 4 syncs/tile.

#define THREADS 768
#define GRIDX   37
#define TPT     96
#define TOTAL_TOK 32768

#define OFF_LS   0          // 10240 floats
#define OFF_RS   10240      // 10240 floats
#define OFF_H2   20480      // 12288 ull = 24576 floats
#define OFF_OUT  45056      // 12288 floats
#define SMEM_FLOATS 57344
#define SMEM_BYTES  (SMEM_FLOATS * 4)   // 229376 B

typedef unsigned long long ull;

__device__ __forceinline__ ull pack2(float v) {
    ull r; asm("mov.b64 %0, {%1, %1};" : "=l"(r) : "f"(v)); return r;
}
__device__ __forceinline__ ull packpair(float a, float b) {
    ull r; asm("mov.b64 %0, {%1, %2};" : "=l"(r) : "f"(a), "f"(b)); return r;
}
__device__ __forceinline__ ull ffma2(ull a, ull b, ull c) {
    ull d; asm("fma.rn.f32x2 %0, %1, %2, %3;" : "=l"(d) : "l"(a), "l"(b), "l"(c));
    return d;
}
__device__ __forceinline__ void unpack2(ull v, float& lo, float& hi) {
    asm("mov.b64 {%0, %1}, %2;" : "=f"(lo), "=f"(hi) : "l"(v));
}

__global__ __launch_bounds__(THREADS, 1)
void monarch_kernel(const float* __restrict__ x,
                    const float* __restrict__ Lg,
                    const float* __restrict__ Rg,
                    float* __restrict__ out,
                    int ntiles)
{
    extern __shared__ float sm[];
    float* Ls   = sm + OFF_LS;
    float* Rs   = sm + OFF_RS;
    ull*   h2u  = (ull*)(sm + OFF_H2);
    float* outs = sm + OFF_OUT;

    const int tid  = threadIdx.x;
    const int w    = tid >> 5;
    const int lane = tid & 31;
    const int qb   = blockIdx.y * 8;

    // ---- one-time weight staging into stride-10 rows ----
    // Ls[(k*32+m)*10 + q] = Lg[m*1024 + (qb+q)*32 + k]
    for (int j = tid; j < 8192; j += THREADS) {
        int m = j >> 8;
        int r = j & 255;                 // q*32 + k
        int q = r >> 5, k = r & 31;
        Ls[(k * 32 + m) * 10 + q] = Lg[m * 1024 + qb * 32 + r];
    }
    // Rs[(p*32+m)*10 + q] = Rg[(qb+q)*1024 + p*32 + m]
    for (int j = tid; j < 8192; j += THREADS) {
        int q = j >> 10;
        int r = j & 1023;                // p*32 + m
        Rs[r * 10 + q] = Rg[(qb + q) * 1024 + r];
    }
    __syncthreads();

    int tile = blockIdx.x;

    // x register double buffer: xr[buf][t*2+kk], tokens [4w,4w+4), 2-k chunks
    float xr[2][8];
    {
        int st = (tile < ntiles) ? tile : 0;
        int tb = st * TPT + 4 * w;
        if (tb > TOTAL_TOK - 4) tb = TOTAL_TOK - 4;
        const float* pb = x + (size_t)tb * 1024 + lane;
        #pragma unroll
        for (int t = 0; t < 4; t++)
            #pragma unroll
            for (int kk = 0; kk < 2; kk++)
                xr[0][t * 2 + kk] = pb[t * 1024 + kk * 32];
    }

    for (; tile < ntiles; tile += GRIDX) {
        // ===================== stage 1 =====================
        ull acc[4][4];                   // [qpair][token]
        #pragma unroll
        for (int qp = 0; qp < 4; qp++)
            #pragma unroll
            for (int t = 0; t < 4; t++) acc[qp][t] = 0ull;

        const float* Lbase = Ls + lane * 10;   // + k*320 + 2*qp

        #pragma unroll 4
        for (int c = 0; c < 16; c++) {
            const int cb = c & 1;
            // prefetch next 2-k chunk (or next tile chunk 0), clamped
            {
                int ptile = (c < 15) ? tile : (tile + GRIDX);
                int pk    = (c < 15) ? 2 * (c + 1) : 0;
                int st    = (ptile < ntiles) ? ptile : 0;
                int tb    = st * TPT + 4 * w;
                if (tb > TOTAL_TOK - 4) tb = TOTAL_TOK - 4;
                const float* pb = x + (size_t)tb * 1024 + pk * 32 + lane;
                #pragma unroll
                for (int t = 0; t < 4; t++)
                    #pragma unroll
                    for (int kk = 0; kk < 2; kk++)
                        xr[cb ^ 1][t * 2 + kk] = pb[t * 1024 + kk * 32];
            }
            // compute k = 2c, 2c+1
            #pragma unroll
            for (int kk = 0; kk < 2; kk++) {
                const int k = 2 * c + kk;
                const float* lp = Lbase + k * 320;
                ull Lq[4];
                #pragma unroll
                for (int qp = 0; qp < 4; qp++)
                    Lq[qp] = *(const ull*)(lp + 2 * qp);   // (L[q],L[q+1])
                ull xv[4];
                #pragma unroll
                for (int t = 0; t < 4; t++)
                    xv[t] = pack2(xr[cb][t * 2 + kk]);     // dup token value
                #pragma unroll
                for (int qp = 0; qp < 4; qp++)
                    #pragma unroll
                    for (int t = 0; t < 4; t++)
                        acc[qp][t] = ffma2(Lq[qp], xv[t], acc[qp][t]);
            }
        }

        // h2[qp][tok][m] <- acc  (ull STS, conflict-free)
        #pragma unroll
        for (int qp = 0; qp < 4; qp++)
            #pragma unroll
            for (int t = 0; t < 4; t++)
                h2u[(qp * 96 + 4 * w + t) * 32 + lane] = acc[qp][t];
        __syncthreads();                 // sync1: h2 complete

        // ===================== stage 2 =====================
        const int qp2 = w & 3;
        const int tg  = w >> 2;          // 0..5: 16-token group
        const float* Rbase = Rs + lane * 320 + 2 * qp2;   // p = lane
        const ull*   h2w   = h2u + (qp2 * 96 + 16 * tg) * 32;
        const int    xq0   = lane ^ ((2 * qp2) << 2);
        const int    xq1   = lane ^ ((2 * qp2 + 1) << 2);

        #pragma unroll
        for (int ph = 0; ph < 2; ph++) {
            ull a2[8];
            #pragma unroll
            for (int j = 0; j < 8; j++) a2[j] = 0ull;

            #pragma unroll 4
            for (int mp = 0; mp < 16; mp++) {        // m = 2*mp
                ull R0 = *(const ull*)(Rbase + mp * 20);
                ull R1 = *(const ull*)(Rbase + mp * 20 + 10);
                #pragma unroll
                for (int j = 0; j < 8; j++) {
                    float4 hh = *(const float4*)(h2w + (8 * ph + j) * 32 + 2 * mp);
                    a2[j] = ffma2(R0, packpair(hh.x, hh.y), a2[j]);
                    a2[j] = ffma2(R1, packpair(hh.z, hh.w), a2[j]);
                }
            }
            // outs[slot][q][p^ (q<<2)], slot = tg*8 + j
            #pragma unroll
            for (int j = 0; j < 8; j++) {
                float f0, f1; unpack2(a2[j], f0, f1);
                int slot = tg * 8 + j;
                outs[slot * 256 + (2 * qp2)     * 32 + xq0] = f0;
                outs[slot * 256 + (2 * qp2 + 1) * 32 + xq1] = f1;
            }
            __syncthreads();             // outs(ph) complete

            // writeout: 48 tokens, slot -> token = 16*(slot>>3) + (slot&7) + 8*ph
            {
                const int gt0 = tile * TPT + 8 * ph;
                #pragma unroll
                for (int i = 0; i < 16; i++) {
                    int lin  = tid + i * THREADS;    // < 12288
                    int q    = lin & 7;
                    int p    = (lin >> 3) & 31;
                    int slot = lin >> 8;
                    int gt   = gt0 + 16 * (slot >> 3) + (slot & 7);
                    float v  = outs[slot * 256 + q * 32 + (p ^ (q << 2))];
                    if (gt < TOTAL_TOK)
                        out[(size_t)gt * 1024 + p * 32 + qb + q] = v;
                }
            }
            if (ph == 0) __syncthreads();    // outs reusable for phase B
            // ph==1: next conflicting access is after sync1 of next tile.
        }
    }
}

extern "C" void kernel_launch(void* const* d_in, const int* in_sizes, int n_in,
                              void* d_out, int out_size)
{
    const float* x  = (const float*)d_in[0];
    const float* Lg = (const float*)d_in[1];
    const float* Rg = (const float*)d_in[2];
    float* out      = (float*)d_out;

    const int tokens = in_sizes[0] / 1024;            // 32768
    const int ntiles = (tokens + TPT - 1) / TPT;      // 342

    cudaFuncSetAttribute(monarch_kernel,
                         cudaFuncAttributeMaxDynamicSharedMemorySize, SMEM_BYTES);

    dim3 grid(GRIDX, 4);
    monarch_kernel<<<grid, THREADS, SMEM_BYTES>>>(x, Lg, Rg, out, ntiles);
}